// round 9
// baseline (speedup 1.0000x reference)
#include <cuda_runtime.h>
#include <cuda_fp16.h>
#include <cstdint>
#include <cstddef>

#define BATCH     131072
#define FDIM      512
#define F2DIM     256
#define OBJ_DIM   100000
#define PRED_DIM  2000
#define EPS_F     1e-5f

// ---------------- device scratch (static, no allocation) ----------------
__device__ int   d_cnt_s[OBJ_DIM];
__device__ int   d_cnt_o[OBJ_DIM];
__device__ int   d_cnt_p[PRED_DIM + 16];
__device__ __align__(16) float d_sumb[3][FDIM];
__device__ __align__(16) float d_sqb [3][FDIM];
__device__ __align__(16) __half d_W4h[F2DIM * FDIM];         // fp16 W4, row-major [256][512]
__device__ __align__(16) __half d_yh[(size_t)BATCH * F2DIM]; // pre-BN layer-4 out, fp16, 64 MB
__device__ float d_sum4[F2DIM];
__device__ float d_sq4 [F2DIM];

// ---------------- helpers ----------------
__device__ __forceinline__ uint32_t smem_u32(const void* p) {
    uint32_t a;
    asm("{ .reg .u64 t; cvta.to.shared.u64 t, %1; cvt.u32.u64 %0, t; }" : "=r"(a) : "l"(p));
    return a;
}
__device__ __forceinline__ void cp16(uint32_t dst, const void* src) {
    asm volatile("cp.async.cg.shared.global [%0], [%1], 16;" :: "r"(dst), "l"(src) : "memory");
}
__device__ __forceinline__ void cp_commit() {
    asm volatile("cp.async.commit_group;" ::: "memory");
}
__device__ __forceinline__ float relu_aff(float a, float w, float c) {
    return fmaxf(fmaf(a, w, c), 0.f);
}
__device__ __forceinline__ void ldsm4(uint32_t& r0, uint32_t& r1, uint32_t& r2, uint32_t& r3,
                                      uint32_t addr) {
    asm volatile("ldmatrix.sync.aligned.m8n8.x4.shared.b16 {%0,%1,%2,%3}, [%4];"
                 : "=r"(r0), "=r"(r1), "=r"(r2), "=r"(r3) : "r"(addr));
}

// ---------------- kernel 0: zero scratch + W4 -> fp16 ----------------
__global__ void __launch_bounds__(256) k_zero(const float* __restrict__ W4) {
    int i = blockIdx.x * blockDim.x + threadIdx.x;   // grid 512*256 = 131072
    if (i < OBJ_DIM) { d_cnt_s[i] = 0; d_cnt_o[i] = 0; }
    if (i < PRED_DIM + 16) d_cnt_p[i] = 0;
    if (i < FDIM) {
        #pragma unroll
        for (int b = 0; b < 3; b++) { d_sumb[b][i] = 0.f; d_sqb[b][i] = 0.f; }
    }
    if (i < F2DIM) { d_sum4[i] = 0.f; d_sq4[i] = 0.f; }
    d_W4h[i] = __float2half_rn(W4[i]);
}

// ---------------- kernel 1: index histograms ----------------
__global__ void k_hist(const int* __restrict__ subj, const int* __restrict__ obj,
                       const int* __restrict__ predi) {
    int i = blockIdx.x * blockDim.x + threadIdx.x;
    if (i < BATCH) {
        atomicAdd(&d_cnt_s[subj[i]], 1);
        atomicAdd(&d_cnt_o[obj[i]], 1);
        atomicAdd(&d_cnt_p[predi[i]], 1);
    }
}

// ---------------- kernel 2: count-weighted column stats (counts prefetched) ----------------
__global__ void __launch_bounds__(128) k_cs(const float* __restrict__ W1,
                                            const float* __restrict__ W2,
                                            const float* __restrict__ W3,
                                            int S1, int S2) {
    const float* W; const int* cnt; int sel, bid, nblk, R;
    if ((int)blockIdx.x < S1)      { W = W1; cnt = d_cnt_s; sel = 0; bid = blockIdx.x;      nblk = S1;             R = OBJ_DIM; }
    else if ((int)blockIdx.x < S2) { W = W2; cnt = d_cnt_o; sel = 1; bid = blockIdx.x - S1; nblk = S2 - S1;        R = OBJ_DIM; }
    else                           { W = W3; cnt = d_cnt_p; sel = 2; bid = blockIdx.x - S2; nblk = gridDim.x - S2; R = PRED_DIM; }
    const int t = threadIdx.x;
    const int step = nblk * 8;
    float4 s = make_float4(0.f, 0.f, 0.f, 0.f);
    float4 q = make_float4(0.f, 0.f, 0.f, 0.f);
    int base = bid * 8;
    int4 ca, cb;
    if (base < R) { ca = *(const int4*)(cnt + base); cb = *(const int4*)(cnt + base + 4); }
    for (; base < R; base += step) {
        int4 na, nb;
        if (base + step < R) {   // prefetch next counts, breaks the latency chain
            na = *(const int4*)(cnt + base + step);
            nb = *(const int4*)(cnt + base + step + 4);
        }
        int cc[8] = {ca.x, ca.y, ca.z, ca.w, cb.x, cb.y, cb.z, cb.w};
        float4 v[8];
        #pragma unroll
        for (int u = 0; u < 8; u++)
            if (cc[u]) v[u] = __ldg((const float4*)(W + (size_t)(base + u) * FDIM) + t);
        #pragma unroll
        for (int u = 0; u < 8; u++) {
            if (cc[u]) {
                float fc = (float)cc[u];
                s.x += fc * v[u].x; s.y += fc * v[u].y; s.z += fc * v[u].z; s.w += fc * v[u].w;
                q.x += fc * v[u].x * v[u].x; q.y += fc * v[u].y * v[u].y;
                q.z += fc * v[u].z * v[u].z; q.w += fc * v[u].w * v[u].w;
            }
        }
        ca = na; cb = nb;
    }
    int c0 = t * 4;
    atomicAdd(&d_sumb[sel][c0 + 0], s.x);
    atomicAdd(&d_sumb[sel][c0 + 1], s.y);
    atomicAdd(&d_sumb[sel][c0 + 2], s.z);
    atomicAdd(&d_sumb[sel][c0 + 3], s.w);
    atomicAdd(&d_sqb[sel][c0 + 0], q.x);
    atomicAdd(&d_sqb[sel][c0 + 1], q.y);
    atomicAdd(&d_sqb[sel][c0 + 2], q.z);
    atomicAdd(&d_sqb[sel][c0 + 3], q.w);
}

// ---------------- kernel 3: FUSED gather + BN-relu + GEMM + stats (64-row, 2 CTAs/SM) ----------------
// SMEM map (bytes):
//   [0, 66560)            A tile: 64 rows x 520 halfs (1040 B/row; 65 x 16B units -> LDSM conflict-free)
//   [66560, 103424)       shared: gather ring (3 x 12288) THEN B chunk buffer (36864)
//   [103424, 104192)      idx[3][64]
//   [104192, 106240)      colsum[256], colsq[256]
#define F_ROWS   64
#define AST      520
#define SM_SHR   66560
#define STG_B    12288
#define SM_IDX   103424
#define SM_SUM   104192
#define SM_SQ    105216
#define SM_TOT   106240

__global__ void __launch_bounds__(512, 2) k_fused(
    const int* __restrict__ subj, const int* __restrict__ obj, const int* __restrict__ predi,
    const float* __restrict__ W1, const float* __restrict__ W2, const float* __restrict__ W3,
    const float* __restrict__ g1, const float* __restrict__ be1,
    const float* __restrict__ g2, const float* __restrict__ be2,
    const float* __restrict__ g3, const float* __restrict__ be3)
{
    extern __shared__ char sm[];
    const uint32_t smb = smem_u32(sm);
    __half* A = (__half*)sm;
    int*   idxs = (int*)(sm + SM_IDX);
    float* colsum = (float*)(sm + SM_SUM);
    float* colsq  = (float*)(sm + SM_SQ);
    const int tid = threadIdx.x, lane = tid & 31, wid = tid >> 5;
    const int i0 = blockIdx.x * F_ROWS;

    if (tid < 192) {
        int tab = tid >> 6, r = tid & 63;
        const int* src = (tab == 0) ? subj : (tab == 1) ? obj : predi;
        idxs[tid] = src[i0 + r];
    }
    if (tid < 256) { colsum[tid] = 0.f; colsq[tid] = 0.f; }

    // per-thread BN-relu affine coefs for column group c4 (registers only)
    const int c4 = tid & 127, k0 = c4 * 4;
    float4 A1, C1, A2, C2, A3, C3;
    {
        auto mk = [&](int b, const float* gp, const float* bp, float4& Ar, float4& Cr) {
            float4 sb = *(const float4*)&d_sumb[b][k0];
            float4 qb = *(const float4*)&d_sqb[b][k0];
            float4 gg = *(const float4*)(gp + k0);
            float4 bb = *(const float4*)(bp + k0);
            auto one = [&](float su, float qu, float gu, float bu, float& a, float& c) {
                float m = su * (1.f / BATCH);
                float v = qu * (1.f / BATCH) - m * m;
                a = gu * rsqrtf(v + EPS_F);
                c = bu - a * m;
            };
            one(sb.x, qb.x, gg.x, bb.x, Ar.x, Cr.x);
            one(sb.y, qb.y, gg.y, bb.y, Ar.y, Cr.y);
            one(sb.z, qb.z, gg.z, bb.z, Ar.z, Cr.z);
            one(sb.w, qb.w, gg.w, bb.w, Ar.w, Cr.w);
        };
        mk(0, g1, be1, A1, C1);
        mk(1, g2, be2, A2, C2);
        mk(2, g3, be3, A3, C3);
    }
    __syncthreads();

    // ===== phase 1: gather -> BN-relu-sum -> fp16 A tile (32 stages x 2 rows, 3-ring) =====
    const int ris = (tid >> 7) & 1;

    auto issue = [&](int s) {
        uint32_t dstb = smb + SM_SHR + (s % 3) * STG_B;
        // 768 float4 slots: 2 rows x 3 tables x 128 cols
        {
            int lin = tid;
            int rr = lin / 384, rem = lin - rr * 384;
            int tab = rem >> 7, cc = rem & 127;
            int gi = idxs[tab * 64 + s * 2 + rr];
            const float* Wt = (tab == 0) ? W1 : (tab == 1) ? W2 : W3;
            cp16(dstb + lin * 16, Wt + (size_t)gi * FDIM + cc * 4);
        }
        if (tid < 256) {
            int lin = tid + 512;
            int rr = 1, rem = lin - 384;
            int tab = rem >> 7, cc = rem & 127;
            int gi = idxs[tab * 64 + s * 2 + rr];
            const float* Wt = (tab == 0) ? W1 : (tab == 1) ? W2 : W3;
            cp16(dstb + lin * 16, Wt + (size_t)gi * FDIM + cc * 4);
        }
        cp_commit();
    };

    issue(0); issue(1);
    #pragma unroll 1
    for (int s = 0; s < 32; s++) {
        if (s + 2 < 32) issue(s + 2);
        if (s < 30)       asm volatile("cp.async.wait_group 2;" ::: "memory");
        else if (s == 30) asm volatile("cp.async.wait_group 1;" ::: "memory");
        else              asm volatile("cp.async.wait_group 0;" ::: "memory");
        __syncthreads();
        if (tid < 256) {
            const float4* st4 = (const float4*)(sm + SM_SHR + (s % 3) * STG_B);
            float4 w1 = st4[ris * 384 + c4];
            float4 w2 = st4[ris * 384 + 128 + c4];
            float4 w3 = st4[ris * 384 + 256 + c4];
            float f0 = relu_aff(A1.x, w1.x, C1.x) + relu_aff(A2.x, w2.x, C2.x) + relu_aff(A3.x, w3.x, C3.x);
            float f1 = relu_aff(A1.y, w1.y, C1.y) + relu_aff(A2.y, w2.y, C2.y) + relu_aff(A3.y, w3.y, C3.y);
            float f2 = relu_aff(A1.z, w1.z, C1.z) + relu_aff(A2.z, w2.z, C2.z) + relu_aff(A3.z, w3.z, C3.z);
            float f3 = relu_aff(A1.w, w1.w, C1.w) + relu_aff(A2.w, w2.w, C2.w) + relu_aff(A3.w, w3.w, C3.w);
            __half2 h0 = __floats2half2_rn(f0, f1);
            __half2 h1 = __floats2half2_rn(f2, f3);
            uint2 u;
            u.x = *(unsigned*)&h0;
            u.y = *(unsigned*)&h1;
            *(uint2*)(A + (s * 2 + ris) * AST + k0) = u;
        }
        __syncthreads();
    }

    // ===== phase 2: GEMM y[64x256] = A[64x512] @ W4h^T (ldmatrix + HMMA) =====
    // 16 warps: wm = wid&1 (32-row strip), wn = wid>>1 (32-col strip)
    const int wm = wid & 1, wn = wid >> 1, g = lane >> 2, tig = lane & 3;
    const uint32_t Bsm = smb + SM_SHR;   // B chunk: 256 rows x 72-half stride (9 x 16B, conflict-free)

    float acc[2][4][4];
    #pragma unroll
    for (int mt = 0; mt < 2; mt++)
        #pragma unroll
        for (int nt = 0; nt < 4; nt++)
            #pragma unroll
            for (int u = 0; u < 4; u++) acc[mt][nt][u] = 0.f;

    // hoisted ldmatrix lane addressing
    const int lm_r = lane & 15;          // row within 16
    const int lm_c = (lane >> 4) * 16;   // 0 or 16 bytes (k offset 8 halfs)
    const uint32_t a_lane_base = smb + (wm * 32 + lm_r) * (AST * 2) + lm_c;
    const uint32_t b_lane_base = Bsm + (wn * 32 + lm_r) * 144 + lm_c;

    #pragma unroll 1
    for (int c = 0; c < 8; c++) {
        // stage B chunk (single buffer; W4h is L2-resident)
        #pragma unroll
        for (int u = 0; u < 4; u++) {
            int idx = tid + 512 * u;             // 0..2047 slots
            int n = idx >> 3, o = idx & 7;
            cp16(Bsm + n * 144 + o * 16, d_W4h + n * FDIM + c * 64 + o * 8);
        }
        cp_commit();
        asm volatile("cp.async.wait_group 0;" ::: "memory");
        __syncthreads();
        #pragma unroll
        for (int ki = 0; ki < 4; ki++) {
            uint32_t a0[4], a1[4], b0[4], b1[4];
            ldsm4(a0[0], a0[1], a0[2], a0[3], a_lane_base + c * 128 + ki * 32);
            ldsm4(a1[0], a1[1], a1[2], a1[3], a_lane_base + 16 * (AST * 2) + c * 128 + ki * 32);
            ldsm4(b0[0], b0[1], b0[2], b0[3], b_lane_base + ki * 32);
            ldsm4(b1[0], b1[1], b1[2], b1[3], b_lane_base + 16 * 144 + ki * 32);
            // b regs: pair p covers nt=2p (b0=r0,b1=r2) and nt=2p+1 (b0=r1,b1=r3)
            uint32_t* ar[2] = {a0, a1};
            uint32_t* br[2] = {b0, b1};
            #pragma unroll
            for (int mt = 0; mt < 2; mt++) {
                #pragma unroll
                for (int nt = 0; nt < 4; nt++) {
                    uint32_t bb0 = br[nt >> 1][nt & 1];
                    uint32_t bb1 = br[nt >> 1][(nt & 1) + 2];
                    asm volatile(
                        "mma.sync.aligned.m16n8k16.row.col.f32.f16.f16.f32 "
                        "{%0,%1,%2,%3}, {%4,%5,%6,%7}, {%8,%9}, {%0,%1,%2,%3};\n"
                        : "+f"(acc[mt][nt][0]), "+f"(acc[mt][nt][1]),
                          "+f"(acc[mt][nt][2]), "+f"(acc[mt][nt][3])
                        : "r"(ar[mt][0]), "r"(ar[mt][1]), "r"(ar[mt][2]), "r"(ar[mt][3]),
                          "r"(bb0), "r"(bb1));
                }
            }
        }
        __syncthreads();
    }

    // ===== epilogue: store y (fp16) + column sum/sumsq (fp32 from accs) =====
    #pragma unroll
    for (int nt = 0; nt < 4; nt++) {
        int col = wn * 32 + nt * 8 + tig * 2;
        float s0 = 0.f, s1 = 0.f, q0 = 0.f, q1 = 0.f;
        #pragma unroll
        for (int mt = 0; mt < 2; mt++) {
            float c0 = acc[mt][nt][0], c1 = acc[mt][nt][1];
            float c2 = acc[mt][nt][2], c3 = acc[mt][nt][3];
            int r = i0 + wm * 32 + mt * 16 + g;
            *(__half2*)(d_yh + (size_t)r * F2DIM + col)       = __floats2half2_rn(c0, c1);
            *(__half2*)(d_yh + (size_t)(r + 8) * F2DIM + col) = __floats2half2_rn(c2, c3);
            s0 += c0 + c2;  s1 += c1 + c3;
            q0 += c0 * c0 + c2 * c2;  q1 += c1 * c1 + c3 * c3;
        }
        #pragma unroll
        for (int off = 4; off < 32; off <<= 1) {
            s0 += __shfl_xor_sync(0xffffffffu, s0, off);
            s1 += __shfl_xor_sync(0xffffffffu, s1, off);
            q0 += __shfl_xor_sync(0xffffffffu, q0, off);
            q1 += __shfl_xor_sync(0xffffffffu, q1, off);
        }
        if (lane < 4) {
            atomicAdd(&colsum[col], s0);
            atomicAdd(&colsum[col + 1], s1);
            atomicAdd(&colsq[col], q0);
            atomicAdd(&colsq[col + 1], q1);
        }
    }
    __syncthreads();
    if (tid < 256) { atomicAdd(&d_sum4[tid], colsum[tid]); }
    else if (tid < 512) { atomicAdd(&d_sq4[tid - 256], colsq[tid - 256]); }
}

// ---------------- kernel 4: BN4 + relu + W5 dot -> logits ----------------
__global__ void __launch_bounds__(256) k_final(
    const float* __restrict__ g4, const float* __restrict__ be4,
    const float* __restrict__ W5, const float* __restrict__ b5,
    float* __restrict__ out)
{
    const int lane = threadIdx.x & 31;
    const int wid  = threadIdx.x >> 5;
    float a[8], c[8], w[8];
    #pragma unroll
    for (int j = 0; j < 8; j++) {
        int col = lane * 8 + j;
        float m  = d_sum4[col] * (1.0f / BATCH);
        float v  = d_sq4[col] * (1.0f / BATCH) - m * m;
        float aa = g4[col] * rsqrtf(v + EPS_F);
        a[j] = aa;
        c[j] = be4[col] - aa * m;
        w[j] = W5[col];
    }
    float bias = b5[0];
    for (int i = blockIdx.x * 8 + wid; i < BATCH; i += gridDim.x * 8) {
        uint4 raw = *(const uint4*)(d_yh + (size_t)i * F2DIM + lane * 8);
        float2 f0 = __half22float2(*(__half2*)&raw.x);
        float2 f1 = __half22float2(*(__half2*)&raw.y);
        float2 f2 = __half22float2(*(__half2*)&raw.z);
        float2 f3 = __half22float2(*(__half2*)&raw.w);
        float accv =
            fmaxf(fmaf(a[0], f0.x, c[0]), 0.f) * w[0] +
            fmaxf(fmaf(a[1], f0.y, c[1]), 0.f) * w[1] +
            fmaxf(fmaf(a[2], f1.x, c[2]), 0.f) * w[2] +
            fmaxf(fmaf(a[3], f1.y, c[3]), 0.f) * w[3] +
            fmaxf(fmaf(a[4], f2.x, c[4]), 0.f) * w[4] +
            fmaxf(fmaf(a[5], f2.y, c[5]), 0.f) * w[5] +
            fmaxf(fmaf(a[6], f3.x, c[6]), 0.f) * w[6] +
            fmaxf(fmaf(a[7], f3.y, c[7]), 0.f) * w[7];
        #pragma unroll
        for (int off = 16; off; off >>= 1)
            accv += __shfl_xor_sync(0xffffffffu, accv, off);
        if (lane == 0) out[i] = accv + bias;
    }
}

// ---------------- launch ----------------
extern "C" void kernel_launch(void* const* d_in, const int* in_sizes, int n_in,
                              void* d_out, int out_size)
{
    (void)in_sizes; (void)n_in; (void)out_size;
    const int*   subj  = (const int*)d_in[0];
    const int*   obj   = (const int*)d_in[1];
    const int*   predi = (const int*)d_in[2];
    const float* W1    = (const float*)d_in[3];
    const float* g1    = (const float*)d_in[5];
    const float* be1   = (const float*)d_in[6];
    const float* W2    = (const float*)d_in[7];
    const float* g2    = (const float*)d_in[9];
    const float* be2   = (const float*)d_in[10];
    const float* W3    = (const float*)d_in[11];
    const float* g3    = (const float*)d_in[13];
    const float* be3   = (const float*)d_in[14];
    const float* W4    = (const float*)d_in[15];
    const float* g4    = (const float*)d_in[17];
    const float* be4   = (const float*)d_in[18];
    const float* W5    = (const float*)d_in[19];
    const float* b5    = (const float*)d_in[20];
    float* out = (float*)d_out;

    cudaFuncSetAttribute(k_fused, cudaFuncAttributeMaxDynamicSharedMemorySize, SM_TOT);

    k_zero<<<512, 256>>>(W4);                               // 0
    k_hist<<<BATCH / 256, 256>>>(subj, obj, predi);         // 1
    k_cs<<<1792, 128>>>(W1, W2, W3, 864, 1728);             // 2
    k_fused<<<BATCH / F_ROWS, 512, SM_TOT>>>(subj, obj, predi, W1, W2, W3,
                                             g1, be1, g2, be2, g3, be3);   // 3 <- profile target
    k_final<<<2048, 256>>>(g4, be4, W5, b5, out);           // 4
}

// round 10
// speedup vs baseline: 1.0422x; 1.0422x over previous
#include <cuda_runtime.h>
#include <cuda_fp16.h>
#include <cstdint>
#include <cstddef>

#define BATCH     131072
#define FDIM      512
#define F2DIM     256
#define OBJ_DIM   100000
#define PRED_DIM  2000
#define EPS_F     1e-5f

// ---------------- device scratch (static, no allocation) ----------------
__device__ int   d_cnt_s[OBJ_DIM];
__device__ int   d_cnt_o[OBJ_DIM];
__device__ int   d_cnt_p[PRED_DIM + 16];
__device__ __align__(16) float d_sumb[3][FDIM];
__device__ __align__(16) float d_sqb [3][FDIM];
__device__ __align__(16) __half d_W4h[F2DIM * FDIM];         // fp16 W4, row-major [256][512]
__device__ __align__(16) __half d_Af[(size_t)BATCH * FDIM];  // fused fp16 A, 128 MB
__device__ __align__(16) __half d_yh[(size_t)BATCH * F2DIM]; // pre-BN layer-4 out, fp16, 64 MB
__device__ float d_sum4[F2DIM];
__device__ float d_sq4 [F2DIM];

// ---------------- helpers ----------------
__device__ __forceinline__ uint32_t smem_u32(const void* p) {
    uint32_t a;
    asm("{ .reg .u64 t; cvta.to.shared.u64 t, %1; cvt.u32.u64 %0, t; }" : "=r"(a) : "l"(p));
    return a;
}
__device__ __forceinline__ void cp16(uint32_t dst, const void* src) {
    asm volatile("cp.async.cg.shared.global [%0], [%1], 16;" :: "r"(dst), "l"(src) : "memory");
}
__device__ __forceinline__ void cp_commit() {
    asm volatile("cp.async.commit_group;" ::: "memory");
}
__device__ __forceinline__ float relu_aff(float a, float w, float c) {
    return fmaxf(fmaf(a, w, c), 0.f);
}
__device__ __forceinline__ void ldsm4(uint32_t& r0, uint32_t& r1, uint32_t& r2, uint32_t& r3,
                                      uint32_t addr) {
    asm volatile("ldmatrix.sync.aligned.m8n8.x4.shared.b16 {%0,%1,%2,%3}, [%4];"
                 : "=r"(r0), "=r"(r1), "=r"(r2), "=r"(r3) : "r"(addr));
}

// ---------------- kernel 0: zero scratch + W4 -> fp16 ----------------
__global__ void __launch_bounds__(256) k_zero(const float* __restrict__ W4) {
    int i = blockIdx.x * blockDim.x + threadIdx.x;   // grid 512*256 = 131072
    if (i < OBJ_DIM) { d_cnt_s[i] = 0; d_cnt_o[i] = 0; }
    if (i < PRED_DIM + 16) d_cnt_p[i] = 0;
    if (i < FDIM) {
        #pragma unroll
        for (int b = 0; b < 3; b++) { d_sumb[b][i] = 0.f; d_sqb[b][i] = 0.f; }
    }
    if (i < F2DIM) { d_sum4[i] = 0.f; d_sq4[i] = 0.f; }
    d_W4h[i] = __float2half_rn(W4[i]);
}

// ---------------- kernel 1: index histograms ----------------
__global__ void k_hist(const int* __restrict__ subj, const int* __restrict__ obj,
                       const int* __restrict__ predi) {
    int i = blockIdx.x * blockDim.x + threadIdx.x;
    if (i < BATCH) {
        atomicAdd(&d_cnt_s[subj[i]], 1);
        atomicAdd(&d_cnt_o[obj[i]], 1);
        atomicAdd(&d_cnt_p[predi[i]], 1);
    }
}

// ---------------- kernel 2: count-weighted column stats (16 rows in flight) ----------------
__global__ void __launch_bounds__(128) k_cs(const float* __restrict__ W1,
                                            const float* __restrict__ W2,
                                            const float* __restrict__ W3,
                                            int S1, int S2) {
    const float* W; const int* cnt; int sel, bid, nblk, R;
    if ((int)blockIdx.x < S1)      { W = W1; cnt = d_cnt_s; sel = 0; bid = blockIdx.x;      nblk = S1;             R = OBJ_DIM; }
    else if ((int)blockIdx.x < S2) { W = W2; cnt = d_cnt_o; sel = 1; bid = blockIdx.x - S1; nblk = S2 - S1;        R = OBJ_DIM; }
    else                           { W = W3; cnt = d_cnt_p; sel = 2; bid = blockIdx.x - S2; nblk = gridDim.x - S2; R = PRED_DIM; }
    const int t = threadIdx.x;
    const int step = nblk * 16;
    float4 s = make_float4(0.f, 0.f, 0.f, 0.f);
    float4 q = make_float4(0.f, 0.f, 0.f, 0.f);
    int base = bid * 16;
    int4 c0, c1, c2, c3;
    if (base < R) {
        c0 = *(const int4*)(cnt + base);      c1 = *(const int4*)(cnt + base + 4);
        c2 = *(const int4*)(cnt + base + 8);  c3 = *(const int4*)(cnt + base + 12);
    }
    for (; base < R; base += step) {
        int4 n0, n1, n2, n3;
        if (base + step < R) {   // prefetch next counts, breaks the latency chain
            n0 = *(const int4*)(cnt + base + step);      n1 = *(const int4*)(cnt + base + step + 4);
            n2 = *(const int4*)(cnt + base + step + 8);  n3 = *(const int4*)(cnt + base + step + 12);
        }
        int cc[16] = {c0.x, c0.y, c0.z, c0.w, c1.x, c1.y, c1.z, c1.w,
                      c2.x, c2.y, c2.z, c2.w, c3.x, c3.y, c3.z, c3.w};
        float4 v[16];
        #pragma unroll
        for (int u = 0; u < 16; u++)
            if (cc[u]) v[u] = __ldg((const float4*)(W + (size_t)(base + u) * FDIM) + t);
        #pragma unroll
        for (int u = 0; u < 16; u++) {
            if (cc[u]) {
                float fc = (float)cc[u];
                s.x += fc * v[u].x; s.y += fc * v[u].y; s.z += fc * v[u].z; s.w += fc * v[u].w;
                q.x += fc * v[u].x * v[u].x; q.y += fc * v[u].y * v[u].y;
                q.z += fc * v[u].z * v[u].z; q.w += fc * v[u].w * v[u].w;
            }
        }
        c0 = n0; c1 = n1; c2 = n2; c3 = n3;
    }
    int cb = t * 4;
    atomicAdd(&d_sumb[sel][cb + 0], s.x);
    atomicAdd(&d_sumb[sel][cb + 1], s.y);
    atomicAdd(&d_sumb[sel][cb + 2], s.z);
    atomicAdd(&d_sumb[sel][cb + 3], s.w);
    atomicAdd(&d_sqb[sel][cb + 0], q.x);
    atomicAdd(&d_sqb[sel][cb + 1], q.y);
    atomicAdd(&d_sqb[sel][cb + 2], q.z);
    atomicAdd(&d_sqb[sel][cb + 3], q.w);
}

// ---------------- kernel 3: cp.async-pipelined gather + BN-relu -> fp16 A ----------------
// PROVEN at 101.5us / 72.5% DRAM (round 5) — unchanged.
#define G_ROWS   64
#define G_SR     4
#define G_NSTG   16
#define STG_B    (G_SR * 3 * FDIM * 4)        // 24576 bytes per stage
#define G_COEF   (3 * STG_B)                  // 73728
#define G_IDX    (G_COEF + 12288)             // 86016
#define G_SMEM   (G_IDX + 768)                // 86784

__global__ void __launch_bounds__(256) k_gather(
    const int* __restrict__ subj, const int* __restrict__ obj, const int* __restrict__ predi,
    const float* __restrict__ W1, const float* __restrict__ W2, const float* __restrict__ W3,
    const float* __restrict__ g1, const float* __restrict__ be1,
    const float* __restrict__ g2, const float* __restrict__ be2,
    const float* __restrict__ g3, const float* __restrict__ be3)
{
    extern __shared__ char sg[];
    const uint32_t smb = smem_u32(sg);
    float* cA = (float*)(sg + G_COEF);          // [3*512]
    float* cC = (float*)(sg + G_COEF + 6144);
    int*   idxs = (int*)(sg + G_IDX);           // [3][64]
    const int tid = threadIdx.x;
    const int i0 = blockIdx.x * G_ROWS;

    if (tid < G_ROWS) {
        idxs[tid]       = subj[i0 + tid];
        idxs[64 + tid]  = obj[i0 + tid];
        idxs[128 + tid] = predi[i0 + tid];
    }
    for (int t = tid; t < FDIM; t += 256) {
        float m, v, a;
        m = d_sumb[0][t] * (1.f / BATCH); v = d_sqb[0][t] * (1.f / BATCH) - m * m;
        a = g1[t] * rsqrtf(v + EPS_F); cA[t] = a;          cC[t] = be1[t] - a * m;
        m = d_sumb[1][t] * (1.f / BATCH); v = d_sqb[1][t] * (1.f / BATCH) - m * m;
        a = g2[t] * rsqrtf(v + EPS_F); cA[512 + t] = a;    cC[512 + t] = be2[t] - a * m;
        m = d_sumb[2][t] * (1.f / BATCH); v = d_sqb[2][t] * (1.f / BATCH) - m * m;
        a = g3[t] * rsqrtf(v + EPS_F); cA[1024 + t] = a;   cC[1024 + t] = be3[t] - a * m;
    }
    __syncthreads();

    const int c4 = tid & 127;
    const int rs0 = tid >> 7;          // 0..1
    const int k0 = c4 * 4;
    const float4 A1 = *(const float4*)&cA[k0],        C1 = *(const float4*)&cC[k0];
    const float4 A2 = *(const float4*)&cA[512 + k0],  C2 = *(const float4*)&cC[512 + k0];
    const float4 A3 = *(const float4*)&cA[1024 + k0], C3 = *(const float4*)&cC[1024 + k0];

    auto issue = [&](int s) {
        int buf = s % 3;
        uint32_t dstb = smb + buf * STG_B;
        #pragma unroll
        for (int u = 0; u < 6; u++) {
            int lin = tid + 256 * u;            // 0..1535 float4 slots
            int ris = lin / 384;                // row in stage
            int rem = lin - ris * 384;
            int tab = rem >> 7;                 // table 0..2
            int cc  = rem & 127;                // float4 col
            int gi  = idxs[tab * 64 + s * G_SR + ris];
            const float* Wt = (tab == 0) ? W1 : (tab == 1) ? W2 : W3;
            cp16(dstb + lin * 16, Wt + (size_t)gi * FDIM + cc * 4);
        }
        cp_commit();
    };

    issue(0); issue(1);
    #pragma unroll 1
    for (int s = 0; s < G_NSTG; s++) {
        if (s + 2 < G_NSTG) issue(s + 2);
        if (s < G_NSTG - 2)       asm volatile("cp.async.wait_group 2;" ::: "memory");
        else if (s == G_NSTG - 2) asm volatile("cp.async.wait_group 1;" ::: "memory");
        else                      asm volatile("cp.async.wait_group 0;" ::: "memory");
        __syncthreads();
        const float4* st4 = (const float4*)(sg + (s % 3) * STG_B);
        #pragma unroll
        for (int rr = 0; rr < 2; rr++) {
            int ris = rs0 + rr * 2;
            int row = i0 + s * G_SR + ris;
            float4 w1 = st4[ris * 384 + c4];
            float4 w2 = st4[ris * 384 + 128 + c4];
            float4 w3 = st4[ris * 384 + 256 + c4];
            float f0 = relu_aff(A1.x, w1.x, C1.x) + relu_aff(A2.x, w2.x, C2.x) + relu_aff(A3.x, w3.x, C3.x);
            float f1 = relu_aff(A1.y, w1.y, C1.y) + relu_aff(A2.y, w2.y, C2.y) + relu_aff(A3.y, w3.y, C3.y);
            float f2 = relu_aff(A1.z, w1.z, C1.z) + relu_aff(A2.z, w2.z, C2.z) + relu_aff(A3.z, w3.z, C3.z);
            float f3 = relu_aff(A1.w, w1.w, C1.w) + relu_aff(A2.w, w2.w, C2.w) + relu_aff(A3.w, w3.w, C3.w);
            __half2 h0 = __floats2half2_rn(f0, f1);
            __half2 h1 = __floats2half2_rn(f2, f3);
            uint2 u;
            u.x = *(unsigned*)&h0;
            u.y = *(unsigned*)&h1;
            *(uint2*)(d_Af + (size_t)row * FDIM + k0) = u;
        }
        __syncthreads();
    }
}

// ---------------- kernel 4: GEMM y = A * W4^T (ldmatrix + HMMA, 3-deep ring) ----------------
// 128x256 tile, 512 threads (16 warps: wm=wid>>2 32-row strip, wn=wid&3 64-col strip).
#define KC      64
#define SROW    144                          // smem row stride bytes (72 halfs, 9x16B: LDSM conflict-free)
#define A_SZ    (128 * SROW)                 // 18432
#define B_SZ    (F2DIM * SROW)               // 36864
#define STG_SZ  (A_SZ + B_SZ)                // 55296 per stage
#define SM_SUM  (3 * STG_SZ)                 // 165888
#define SM_SQ   (SM_SUM + 1024)
#define SM_TOT  (SM_SQ + 1024)               // 167936

__global__ void __launch_bounds__(512, 1) k_gemm() {
    extern __shared__ char sm[];
    const uint32_t smb = smem_u32(sm);
    const int tid = threadIdx.x, lane = tid & 31, wid = tid >> 5;
    const int i0 = blockIdx.x * 128;
    float* colsum = (float*)(sm + SM_SUM);
    float* colsq  = (float*)(sm + SM_SQ);
    if (tid < 256) colsum[tid] = 0.f;
    else colsq[tid - 256] = 0.f;

    const int wm = wid >> 2, wn = wid & 3, g = lane >> 2, tig = lane & 3;

    auto issue = [&](int c) {
        uint32_t base = smb + (c % 3) * STG_SZ;
        // A chunk: 128 rows x 64 halfs
        #pragma unroll
        for (int u = 0; u < 2; u++) {
            int idx = tid + 512 * u;
            int row = idx >> 3, o = idx & 7;
            cp16(base + row * SROW + o * 16, d_Af + (size_t)(i0 + row) * FDIM + c * KC + o * 8);
        }
        // B chunk: 256 rows x 64 halfs
        #pragma unroll
        for (int u = 0; u < 4; u++) {
            int idx = tid + 512 * u;
            int n = idx >> 3, o = idx & 7;
            cp16(base + A_SZ + n * SROW + o * 16, d_W4h + n * FDIM + c * KC + o * 8);
        }
        cp_commit();
    };

    float acc[2][8][4];
    #pragma unroll
    for (int mt = 0; mt < 2; mt++)
        #pragma unroll
        for (int nt = 0; nt < 8; nt++)
            #pragma unroll
            for (int u = 0; u < 4; u++) acc[mt][nt][u] = 0.f;

    // hoisted ldmatrix lane addressing (validated mapping: lane&15 = row, lane>>4 selects 16B k-half)
    const int lm_r = lane & 15;
    const int lm_c = (lane >> 4) * 16;
    const uint32_t a_off = (wm * 32 + lm_r) * SROW + lm_c;
    const uint32_t b_off = A_SZ + (wn * 64 + lm_r) * SROW + lm_c;

    issue(0); issue(1); issue(2);
    #pragma unroll 1
    for (int c = 0; c < 8; c++) {
        if (c < 6)       asm volatile("cp.async.wait_group 2;" ::: "memory");
        else if (c == 6) asm volatile("cp.async.wait_group 1;" ::: "memory");
        else             asm volatile("cp.async.wait_group 0;" ::: "memory");
        __syncthreads();
        const uint32_t sb = smb + (c % 3) * STG_SZ;
        #pragma unroll
        for (int ki = 0; ki < 4; ki++) {
            uint32_t a0[4], a1[4], b[4][4];
            ldsm4(a0[0], a0[1], a0[2], a0[3], sb + a_off + ki * 32);
            ldsm4(a1[0], a1[1], a1[2], a1[3], sb + a_off + 16 * SROW + ki * 32);
            #pragma unroll
            for (int nb = 0; nb < 4; nb++)
                ldsm4(b[nb][0], b[nb][1], b[nb][2], b[nb][3],
                      sb + b_off + nb * 16 * SROW + ki * 32);
            uint32_t* ar[2] = {a0, a1};
            #pragma unroll
            for (int mt = 0; mt < 2; mt++) {
                #pragma unroll
                for (int nt = 0; nt < 8; nt++) {
                    uint32_t bb0 = b[nt >> 1][nt & 1];
                    uint32_t bb1 = b[nt >> 1][(nt & 1) + 2];
                    asm volatile(
                        "mma.sync.aligned.m16n8k16.row.col.f32.f16.f16.f32 "
                        "{%0,%1,%2,%3}, {%4,%5,%6,%7}, {%8,%9}, {%0,%1,%2,%3};\n"
                        : "+f"(acc[mt][nt][0]), "+f"(acc[mt][nt][1]),
                          "+f"(acc[mt][nt][2]), "+f"(acc[mt][nt][3])
                        : "r"(ar[mt][0]), "r"(ar[mt][1]), "r"(ar[mt][2]), "r"(ar[mt][3]),
                          "r"(bb0), "r"(bb1));
                }
            }
        }
        __syncthreads();
        if (c + 3 < 8) issue(c + 3);
    }

    // epilogue: store y (fp16) + column sum/sumsq (fp32 from accs)
    #pragma unroll
    for (int nt = 0; nt < 8; nt++) {
        int col = wn * 64 + nt * 8 + tig * 2;
        float s0 = 0.f, s1 = 0.f, q0 = 0.f, q1 = 0.f;
        #pragma unroll
        for (int mt = 0; mt < 2; mt++) {
            float c0 = acc[mt][nt][0], c1 = acc[mt][nt][1];
            float c2 = acc[mt][nt][2], c3 = acc[mt][nt][3];
            int r = i0 + wm * 32 + mt * 16 + g;
            *(__half2*)(d_yh + (size_t)r * F2DIM + col)       = __floats2half2_rn(c0, c1);
            *(__half2*)(d_yh + (size_t)(r + 8) * F2DIM + col) = __floats2half2_rn(c2, c3);
            s0 += c0 + c2;  s1 += c1 + c3;
            q0 += c0 * c0 + c2 * c2;  q1 += c1 * c1 + c3 * c3;
        }
        #pragma unroll
        for (int off = 4; off < 32; off <<= 1) {
            s0 += __shfl_xor_sync(0xffffffffu, s0, off);
            s1 += __shfl_xor_sync(0xffffffffu, s1, off);
            q0 += __shfl_xor_sync(0xffffffffu, q0, off);
            q1 += __shfl_xor_sync(0xffffffffu, q1, off);
        }
        if (lane < 4) {
            atomicAdd(&colsum[col], s0);
            atomicAdd(&colsum[col + 1], s1);
            atomicAdd(&colsq[col], q0);
            atomicAdd(&colsq[col + 1], q1);
        }
    }
    __syncthreads();
    if (tid < 256) atomicAdd(&d_sum4[tid], colsum[tid]);
    else atomicAdd(&d_sq4[tid - 256], colsq[tid - 256]);
}

// ---------------- kernel 5: BN4 + relu + W5 dot -> logits ----------------
__global__ void __launch_bounds__(256) k_final(
    const float* __restrict__ g4, const float* __restrict__ be4,
    const float* __restrict__ W5, const float* __restrict__ b5,
    float* __restrict__ out)
{
    const int lane = threadIdx.x & 31;
    const int wid  = threadIdx.x >> 5;
    float a[8], c[8], w[8];
    #pragma unroll
    for (int j = 0; j < 8; j++) {
        int col = lane * 8 + j;
        float m  = d_sum4[col] * (1.0f / BATCH);
        float v  = d_sq4[col] * (1.0f / BATCH) - m * m;
        float aa = g4[col] * rsqrtf(v + EPS_F);
        a[j] = aa;
        c[j] = be4[col] - aa * m;
        w[j] = W5[col];
    }
    float bias = b5[0];
    for (int i = blockIdx.x * 8 + wid; i < BATCH; i += gridDim.x * 8) {
        uint4 raw = *(const uint4*)(d_yh + (size_t)i * F2DIM + lane * 8);
        float2 f0 = __half22float2(*(__half2*)&raw.x);
        float2 f1 = __half22float2(*(__half2*)&raw.y);
        float2 f2 = __half22float2(*(__half2*)&raw.z);
        float2 f3 = __half22float2(*(__half2*)&raw.w);
        float accv =
            fmaxf(fmaf(a[0], f0.x, c[0]), 0.f) * w[0] +
            fmaxf(fmaf(a[1], f0.y, c[1]), 0.f) * w[1] +
            fmaxf(fmaf(a[2], f1.x, c[2]), 0.f) * w[2] +
            fmaxf(fmaf(a[3], f1.y, c[3]), 0.f) * w[3] +
            fmaxf(fmaf(a[4], f2.x, c[4]), 0.f) * w[4] +
            fmaxf(fmaf(a[5], f2.y, c[5]), 0.f) * w[5] +
            fmaxf(fmaf(a[6], f3.x, c[6]), 0.f) * w[6] +
            fmaxf(fmaf(a[7], f3.y, c[7]), 0.f) * w[7];
        #pragma unroll
        for (int off = 16; off; off >>= 1)
            accv += __shfl_xor_sync(0xffffffffu, accv, off);
        if (lane == 0) out[i] = accv + bias;
    }
}

// ---------------- launch ----------------
extern "C" void kernel_launch(void* const* d_in, const int* in_sizes, int n_in,
                              void* d_out, int out_size)
{
    (void)in_sizes; (void)n_in; (void)out_size;
    const int*   subj  = (const int*)d_in[0];
    const int*   obj   = (const int*)d_in[1];
    const int*   predi = (const int*)d_in[2];
    const float* W1    = (const float*)d_in[3];
    const float* g1    = (const float*)d_in[5];
    const float* be1   = (const float*)d_in[6];
    const float* W2    = (const float*)d_in[7];
    const float* g2    = (const float*)d_in[9];
    const float* be2   = (const float*)d_in[10];
    const float* W3    = (const float*)d_in[11];
    const float* g3    = (const float*)d_in[13];
    const float* be3   = (const float*)d_in[14];
    const float* W4    = (const float*)d_in[15];
    const float* g4    = (const float*)d_in[17];
    const float* be4   = (const float*)d_in[18];
    const float* W5    = (const float*)d_in[19];
    const float* b5    = (const float*)d_in[20];
    float* out = (float*)d_out;

    cudaFuncSetAttribute(k_gather, cudaFuncAttributeMaxDynamicSharedMemorySize, G_SMEM);
    cudaFuncSetAttribute(k_gemm, cudaFuncAttributeMaxDynamicSharedMemorySize, SM_TOT);

    k_zero<<<512, 256>>>(W4);                               // 0
    k_hist<<<BATCH / 256, 256>>>(subj, obj, predi);         // 1
    k_cs<<<1792, 128>>>(W1, W2, W3, 864, 1728);             // 2
    k_gather<<<BATCH / G_ROWS, 256, G_SMEM>>>(subj, obj, predi, W1, W2, W3,
                                              g1, be1, g2, be2, g3, be3);  // 3
    k_gemm<<<BATCH / 128, 512, SM_TOT>>>();                 // 4
    k_final<<<2048, 256>>>(g4, be4, W5, b5, out);           // 5
}